// round 13
// baseline (speedup 1.0000x reference)
#include <cuda_runtime.h>
#include <cuda_bf16.h>
#include <cuda_fp16.h>
#include <cstdint>

// NonlocalBlock: B=4, C=256, Ci=128, H=W=64 (N=4096)
// out = BN(w_out @ softmax(theta^T phi) @ g^T) + x
// Proj: HMMA bf16 3-chain (unchanged). Attn: HMMA fp16 2-chain
// (S = th_h*(ph_h+ph_l), Y = P_h*(g_h+g_l)), M=32 rows/warp, 4 warps/block
// to halve smem crossbar traffic (R11/R12 evidence: smem-BW bound).

namespace {
constexpr int B  = 4;
constexpr int C  = 256;
constexpr int CI = 128;
constexpr int N  = 4096;
}

// ---- scratch (static device globals; no runtime allocation allowed) ----
__device__ float d_y[B * CI * N];
__device__ float d_wy[B * C * N];
__device__ float d_psum[C * 128];
__device__ float d_psq[C * 128];
__device__ float d_bnA[C];
__device__ float d_bnB[C];
// fp16 attention operands
__device__ alignas(16) __half d_thT[B * N * CI];      // [b][n][ci]  hi only
__device__ alignas(16) __half d_phT_hi[B * N * CI];   // [b][m][ci]
__device__ alignas(16) __half d_phT_lo[B * N * CI];
__device__ alignas(16) __half d_g16_hi[B * CI * N];   // [b][c][m]
__device__ alignas(16) __half d_g16_lo[B * CI * N];
// bf16 split inputs for HMMA proj
__device__ alignas(16) __nv_bfloat16 d_W_hi[384 * 256];
__device__ alignas(16) __nv_bfloat16 d_W_lo[384 * 256];
__device__ alignas(16) __nv_bfloat16 d_x_hi[B * C * N];   // [b][c][n]
__device__ alignas(16) __nv_bfloat16 d_x_lo[B * C * N];

// ============================================================================
// helpers
// ============================================================================
__device__ __forceinline__ uint32_t smem_u32(const void* p) {
    uint32_t a;
    asm("{ .reg .u64 t; cvta.to.shared.u64 t, %1; cvt.u32.u64 %0, t; }" : "=r"(a) : "l"(p));
    return a;
}
__device__ __forceinline__ uint16_t f2bf(float v) {
    return __bfloat16_as_ushort(__float2bfloat16(v));
}
__device__ __forceinline__ float bf2f(uint16_t u) {
    return __bfloat162float(__ushort_as_bfloat16(u));
}
__device__ __forceinline__ uint16_t f2h(float v) {
    return __half_as_ushort(__float2half_rn(v));
}
__device__ __forceinline__ float h2f(uint16_t u) {
    return __half2float(__ushort_as_half(u));
}
__device__ __forceinline__ uint32_t pack2(uint16_t lo, uint16_t hi) {
    return (uint32_t)lo | ((uint32_t)hi << 16);
}
__device__ __forceinline__ uint32_t f16x2(float lo, float hi) {
    __half2 h = __floats2half2_rn(lo, hi);
    return *reinterpret_cast<uint32_t*>(&h);
}
__device__ __forceinline__ void mma_bf16(float* c,
                                         uint32_t a0, uint32_t a1, uint32_t a2, uint32_t a3,
                                         uint32_t b0, uint32_t b1) {
    asm volatile(
        "mma.sync.aligned.m16n8k16.row.col.f32.bf16.bf16.f32 "
        "{%0,%1,%2,%3}, {%4,%5,%6,%7}, {%8,%9}, {%0,%1,%2,%3};"
        : "+f"(c[0]), "+f"(c[1]), "+f"(c[2]), "+f"(c[3])
        : "r"(a0), "r"(a1), "r"(a2), "r"(a3), "r"(b0), "r"(b1));
}
__device__ __forceinline__ void mma_f16(float* c,
                                        uint32_t a0, uint32_t a1, uint32_t a2, uint32_t a3,
                                        uint32_t b0, uint32_t b1) {
    asm volatile(
        "mma.sync.aligned.m16n8k16.row.col.f32.f16.f16.f32 "
        "{%0,%1,%2,%3}, {%4,%5,%6,%7}, {%8,%9}, {%0,%1,%2,%3};"
        : "+f"(c[0]), "+f"(c[1]), "+f"(c[2]), "+f"(c[3])
        : "r"(a0), "r"(a1), "r"(a2), "r"(a3), "r"(b0), "r"(b1));
}
__device__ __forceinline__ void ldsm_x4(uint32_t addr, uint32_t& r0, uint32_t& r1,
                                        uint32_t& r2, uint32_t& r3) {
    asm volatile("ldmatrix.sync.aligned.m8n8.x4.shared.b16 {%0,%1,%2,%3}, [%4];"
                 : "=r"(r0), "=r"(r1), "=r"(r2), "=r"(r3) : "r"(addr));
}
__device__ __forceinline__ void ldsm_x4_t(uint32_t addr, uint32_t& r0, uint32_t& r1,
                                          uint32_t& r2, uint32_t& r3) {
    asm volatile("ldmatrix.sync.aligned.m8n8.x4.trans.shared.b16 {%0,%1,%2,%3}, [%4];"
                 : "=r"(r0), "=r"(r1), "=r"(r2), "=r"(r3) : "r"(addr));
}
__device__ __forceinline__ void cp16(uint32_t saddr, const void* gaddr) {
    asm volatile("cp.async.cg.shared.global [%0], [%1], 16;" :: "r"(saddr), "l"(gaddr));
}
#define CP_COMMIT() asm volatile("cp.async.commit_group;" ::: "memory")
#define CP_WAIT(n)  asm volatile("cp.async.wait_group %0;" :: "n"(n) : "memory")

// ============================================================================
// K0a: split weights. grid 384 x 256.
// ============================================================================
__global__ void splitw_kernel(const float* __restrict__ w_g,
                              const float* __restrict__ w_t,
                              const float* __restrict__ w_p)
{
    int row = blockIdx.x, t = threadIdx.x;
    const float* src = (row < 128) ? w_g + (size_t)row * 256
                     : (row < 256) ? w_t + (size_t)(row - 128) * 256
                                   : w_p + (size_t)(row - 256) * 256;
    float v = src[t];
    uint16_t h = f2bf(v);
    d_W_hi[(size_t)row * 256 + t] = __ushort_as_bfloat16(h);
    d_W_lo[(size_t)row * 256 + t] = __ushort_as_bfloat16(f2bf(v - bf2f(h)));
}

// ============================================================================
// K0b: split x. grid 4096 x 256.
// ============================================================================
__global__ void splitx_kernel(const float* __restrict__ x)
{
    int idx4 = blockIdx.x * blockDim.x + threadIdx.x;
    float4 v = ((const float4*)x)[idx4];
    uint16_t h0 = f2bf(v.x), h1 = f2bf(v.y), h2 = f2bf(v.z), h3 = f2bf(v.w);
    *(uint2*)(d_x_hi + (size_t)idx4 * 4) = make_uint2(pack2(h0, h1), pack2(h2, h3));
    *(uint2*)(d_x_lo + (size_t)idx4 * 4) =
        make_uint2(pack2(f2bf(v.x - bf2f(h0)), f2bf(v.y - bf2f(h1))),
                   pack2(f2bf(v.z - bf2f(h2)), f2bf(v.w - bf2f(h3))));
}

// ============================================================================
// K1: HMMA projection GEMM (bf16 3-chain, fp16 outputs). grid (3,32,4), 256.
// mt: 0 -> g16 [b][c][m] hi+lo; 1 -> thT [b][n][ci] hi only; 2 -> phT hi+lo
// ============================================================================
#define PJ_WHI   0u
#define PJ_WLO   10240u
#define PJ_XHI   20480u
#define PJ_XLO   29184u
#define PJ_STAGE 37888u
#define PROJ_SMEM 75776

__global__ void __launch_bounds__(256, 2) proj_kernel(const float* __restrict__ b_g,
                                                      const float* __restrict__ b_t,
                                                      const float* __restrict__ b_p)
{
    extern __shared__ char smc[];
    const uint32_t sb = smem_u32(smc);
    const int mt = blockIdx.x;
    const int n0 = blockIdx.y * 128;
    const int b  = blockIdx.z;
    const int tid = threadIdx.x, wid = tid >> 5, lane = tid & 31;
    const int gid = lane >> 2, tig = lane & 3;
    const int obase = mt * 128;

    float acc[16][4];
#pragma unroll
    for (int nf = 0; nf < 16; nf++)
#pragma unroll
        for (int e = 0; e < 4; e++) acc[nf][e] = 0.f;

    auto load_chunk = [&](int st, int kc) {
        uint32_t base = sb + (uint32_t)st * PJ_STAGE;
        for (int idx = tid; idx < 512; idx += 256) {
            int r = idx >> 2, sg = idx & 3;
            cp16(base + PJ_WHI + (uint32_t)r * 80 + sg * 16,
                 d_W_hi + (size_t)(obase + r) * 256 + kc + sg * 8);
            cp16(base + PJ_WLO + (uint32_t)r * 80 + sg * 16,
                 d_W_lo + (size_t)(obase + r) * 256 + kc + sg * 8);
            int xr = idx >> 4, xs = idx & 15;
            cp16(base + PJ_XHI + (uint32_t)xr * 272 + xs * 16,
                 d_x_hi + (size_t)(b * C + kc + xr) * N + n0 + xs * 8);
            cp16(base + PJ_XLO + (uint32_t)xr * 272 + xs * 16,
                 d_x_lo + (size_t)(b * C + kc + xr) * N + n0 + xs * 8);
        }
    };

    load_chunk(0, 0);
    CP_COMMIT();
    for (int c = 0; c < 8; ++c) {
        if (c + 1 < 8) { load_chunk((c + 1) & 1, (c + 1) * 32); CP_COMMIT(); CP_WAIT(1); }
        else           { CP_WAIT(0); }
        __syncthreads();
        uint32_t base = sb + (uint32_t)(c & 1) * PJ_STAGE;
#pragma unroll
        for (int kk = 0; kk < 2; ++kk) {
            uint32_t aaddr = base + PJ_WHI + (uint32_t)(wid * 16 + (lane & 15)) * 80
                           + (uint32_t)(lane >> 4) * 16 + (uint32_t)kk * 32;
            uint32_t ah0, ah1, ah2, ah3, al0, al1, al2, al3;
            ldsm_x4(aaddr, ah0, ah1, ah2, ah3);
            ldsm_x4(aaddr + (PJ_WLO - PJ_WHI), al0, al1, al2, al3);
#pragma unroll
            for (int nf = 0; nf < 16; ++nf) {
                uint32_t baddr = base + PJ_XHI
                               + (uint32_t)(kk * 16 + ((lane >> 3) & 1) * 8 + (lane & 7)) * 272
                               + (uint32_t)(lane >> 4) * (PJ_XLO - PJ_XHI)
                               + (uint32_t)nf * 16;
                uint32_t bh0, bh1, bl0, bl1;
                ldsm_x4_t(baddr, bh0, bh1, bl0, bl1);
                mma_bf16(acc[nf], ah0, ah1, ah2, ah3, bh0, bh1);
                mma_bf16(acc[nf], ah0, ah1, ah2, ah3, bl0, bl1);
                mma_bf16(acc[nf], al0, al1, al2, al3, bh0, bh1);
            }
        }
        __syncthreads();
    }

    const float* bias = (mt == 0) ? b_g : (mt == 1) ? b_t : b_p;
    const int r0 = wid * 16 + gid, r1 = r0 + 8;
    const float br0 = bias[r0], br1 = bias[r1];
#pragma unroll
    for (int nf = 0; nf < 16; ++nf) {
        acc[nf][0] += br0; acc[nf][1] += br0;
        acc[nf][2] += br1; acc[nf][3] += br1;
    }

    if (mt == 0) {
        __half* dsts[2] = { d_g16_hi + (size_t)(b * CI) * N + n0,
                            d_g16_lo + (size_t)(b * CI) * N + n0 };
#pragma unroll
        for (int rnd = 0; rnd < 2; ++rnd) {
#pragma unroll
            for (int nf = 0; nf < 16; ++nf) {
                int ncol = 8 * nf + 2 * tig;
                uint16_t h0 = f2h(acc[nf][0]), h1 = f2h(acc[nf][1]);
                uint16_t h2 = f2h(acc[nf][2]), h3 = f2h(acc[nf][3]);
                uint32_t v0, v1;
                if (rnd == 0) { v0 = pack2(h0, h1); v1 = pack2(h2, h3); }
                else {
                    v0 = pack2(f2h(acc[nf][0] - h2f(h0)), f2h(acc[nf][1] - h2f(h1)));
                    v1 = pack2(f2h(acc[nf][2] - h2f(h2)), f2h(acc[nf][3] - h2f(h3)));
                }
                *(uint32_t*)(smc + (uint32_t)r0 * 272 + (uint32_t)ncol * 2) = v0;
                *(uint32_t*)(smc + (uint32_t)r1 * 272 + (uint32_t)ncol * 2) = v1;
            }
            __syncthreads();
            for (int idx = tid; idx < 2048; idx += 256) {
                int row = idx >> 4, c16 = idx & 15;
                *(uint4*)(dsts[rnd] + (size_t)row * N + c16 * 8) =
                    *(const uint4*)(smc + (uint32_t)row * 272 + (uint32_t)c16 * 16);
            }
            __syncthreads();
        }
    } else {
        __half* dsts[2];
        dsts[0] = (mt == 1) ? d_thT : d_phT_hi;
        dsts[1] = (mt == 1) ? nullptr : d_phT_lo;
        const int nrnd = (mt == 1) ? 1 : 2;
        for (int rnd = 0; rnd < nrnd; ++rnd) {
#pragma unroll
            for (int nf = 0; nf < 16; ++nf) {
                int nc = 8 * nf + 2 * tig;
                uint16_t h0 = f2h(acc[nf][0]), h1 = f2h(acc[nf][1]);
                uint16_t h2 = f2h(acc[nf][2]), h3 = f2h(acc[nf][3]);
                uint16_t v0, v1, v2, v3;
                if (rnd == 0) { v0 = h0; v1 = h1; v2 = h2; v3 = h3; }
                else {
                    v0 = f2h(acc[nf][0] - h2f(h0)); v1 = f2h(acc[nf][1] - h2f(h1));
                    v2 = f2h(acc[nf][2] - h2f(h2)); v3 = f2h(acc[nf][3] - h2f(h3));
                }
                *(uint16_t*)(smc + (uint32_t)(nc + 0) * 272 + (uint32_t)r0 * 2) = v0;
                *(uint16_t*)(smc + (uint32_t)(nc + 1) * 272 + (uint32_t)r0 * 2) = v1;
                *(uint16_t*)(smc + (uint32_t)(nc + 0) * 272 + (uint32_t)r1 * 2) = v2;
                *(uint16_t*)(smc + (uint32_t)(nc + 1) * 272 + (uint32_t)r1 * 2) = v3;
            }
            __syncthreads();
            for (int idx = tid; idx < 2048; idx += 256) {
                int row = idx >> 4, c16 = idx & 15;
                *(uint4*)(dsts[rnd] + (size_t)(b * N + n0 + row) * CI + c16 * 8) =
                    *(const uint4*)(smc + (uint32_t)row * 272 + (uint32_t)c16 * 16);
            }
            __syncthreads();
        }
    }
}

// ============================================================================
// K2: HMMA fp16 flash attention. 4 warps x M=32 rows, 128 threads.
// QK: S = th_h * (ph_h + ph_l)  (2 chains);  exp -> P fp16 in registers
// PV: Y = P_h * (g_h + g_l)     (2 chains), B-frags reused by 2 A-frags.
// grid (32, 4), dyn smem 178688 B, cp.async 2-stage.
// SMEM: TH hi 34816 | 2 stages x (PHI hi/lo 2x17408 + G hi/lo 2x18432) | lred
// ============================================================================
#define AT_TH      0u
#define AT_ST      34816u
#define ST_PHI_HI  0u
#define ST_PHI_LO  17408u
#define ST_G_HI    34816u
#define ST_G_LO    53248u
#define AT_STAGE   71680u
#define AT_LRED    178176u
#define ATTN_SMEM  178688

__global__ void __launch_bounds__(128, 1) attn_kernel()
{
    extern __shared__ char smc[];
    const uint32_t sb = smem_u32(smc);
    const int b   = blockIdx.y;
    const int n0  = blockIdx.x * 128;
    const int tid = threadIdx.x;
    const int wid = tid >> 5, lane = tid & 31;
    const int gid = lane >> 2, tig = lane & 3;
    const int sel = lane >> 3, lr = lane & 7;

    // ---- theta hi tile -> smem once ----
    {
        const __half* th = d_thT + (size_t)(b * N + n0) * CI;
        for (int idx = tid; idx < 128 * 16; idx += 128) {
            int r = idx >> 4, ch = idx & 15;
            cp16(sb + AT_TH + (uint32_t)r * 272 + (uint32_t)ch * 16,
                 th + (size_t)r * CI + ch * 8);
        }
    }
    CP_COMMIT();

    auto stage_load = [&](int st, int it) {
        const int m0 = it * 64;
        uint32_t base = sb + AT_ST + (uint32_t)st * AT_STAGE;
        const __half* ph = d_phT_hi + (size_t)(b * N + m0) * CI;
        const __half* pl = d_phT_lo + (size_t)(b * N + m0) * CI;
        for (int idx = tid; idx < 64 * 16; idx += 128) {
            int r = idx >> 4, ch = idx & 15;
            uint32_t o = (uint32_t)r * 272 + (uint32_t)ch * 16;
            cp16(base + ST_PHI_HI + o, ph + (size_t)r * CI + ch * 8);
            cp16(base + ST_PHI_LO + o, pl + (size_t)r * CI + ch * 8);
        }
        const __half* gh = d_g16_hi + (size_t)b * CI * N + m0;
        const __half* gl = d_g16_lo + (size_t)b * CI * N + m0;
        for (int idx = tid; idx < 128 * 8; idx += 128) {
            int r = idx >> 3, ch = idx & 7;
            uint32_t o = (uint32_t)r * 144 + (uint32_t)ch * 16;
            cp16(base + ST_G_HI + o, gh + (size_t)r * N + ch * 8);
            cp16(base + ST_G_LO + o, gl + (size_t)r * N + ch * 8);
        }
    };

    stage_load(0, 0);
    CP_COMMIT();

    float y[2][16][4];
#pragma unroll
    for (int i = 0; i < 2; i++)
#pragma unroll
        for (int ct = 0; ct < 16; ct++)
#pragma unroll
            for (int e = 0; e < 4; e++) y[i][ct][e] = 0.f;
    float l[2][2] = {{0.f, 0.f}, {0.f, 0.f}};

    // A-frag bases: rows 32*wid + frag*16 + (lane&15)
    const uint32_t a0_base = sb + AT_TH + (uint32_t)(32 * wid + (lane & 15)) * 272
                           + (uint32_t)(lane >> 4) * 16;
    const uint32_t a1_base = a0_base + 16u * 272u;

    for (int it = 0; it < 64; ++it) {
        if (it + 1 < 64) { stage_load((it + 1) & 1, it + 1); CP_COMMIT(); CP_WAIT(1); }
        else             { CP_WAIT(0); }
        __syncthreads();
        const uint32_t stb = sb + AT_ST + (uint32_t)(it & 1) * AT_STAGE;

        // ---- QK: S[32 x 64] ----
        float s[2][8][4];
#pragma unroll
        for (int i = 0; i < 2; i++)
#pragma unroll
            for (int j = 0; j < 8; j++)
#pragma unroll
                for (int e = 0; e < 4; e++) s[i][j][e] = 0.f;

#pragma unroll
        for (int k = 0; k < 8; k++) {
            uint32_t A00, A01, A02, A03, A10, A11, A12, A13;
            ldsm_x4(a0_base + (uint32_t)k * 32, A00, A01, A02, A03);
            ldsm_x4(a1_base + (uint32_t)k * 32, A10, A11, A12, A13);
#pragma unroll
            for (int j = 0; j < 8; j++) {
                uint32_t baddr = stb + ((sel >= 2) ? ST_PHI_LO : ST_PHI_HI)
                               + (uint32_t)(8 * j + lr) * 272
                               + (uint32_t)k * 32 + (uint32_t)(sel & 1) * 16;
                uint32_t bh0, bh1, bl0, bl1;
                ldsm_x4(baddr, bh0, bh1, bl0, bl1);
                mma_f16(s[0][j], A00, A01, A02, A03, bh0, bh1);
                mma_f16(s[0][j], A00, A01, A02, A03, bl0, bl1);
                mma_f16(s[1][j], A10, A11, A12, A13, bh0, bh1);
                mma_f16(s[1][j], A10, A11, A12, A13, bl0, bl1);
            }
        }

        // ---- exp + rowsums + pack P (fp16 A-frags, registers only) ----
        uint32_t pa[2][4][4];
#pragma unroll
        for (int i = 0; i < 2; i++) {
#pragma unroll
            for (int j = 0; j < 8; j++) {
#pragma unroll
                for (int e = 0; e < 4; e++) s[i][j][e] = __expf(s[i][j][e]);
                l[i][0] += s[i][j][0] + s[i][j][1];
                l[i][1] += s[i][j][2] + s[i][j][3];
            }
#pragma unroll
            for (int kt = 0; kt < 4; kt++) {
                pa[i][kt][0] = f16x2(s[i][2 * kt][0], s[i][2 * kt][1]);
                pa[i][kt][1] = f16x2(s[i][2 * kt][2], s[i][2 * kt][3]);
                pa[i][kt][2] = f16x2(s[i][2 * kt + 1][0], s[i][2 * kt + 1][1]);
                pa[i][kt][3] = f16x2(s[i][2 * kt + 1][2], s[i][2 * kt + 1][3]);
            }
        }

        // ---- PV: Y[32 x 128] ----
#pragma unroll
        for (int kt = 0; kt < 4; kt++) {
#pragma unroll
            for (int ct = 0; ct < 16; ct++) {
                uint32_t gaddr = stb + ((sel >= 2) ? ST_G_LO : ST_G_HI)
                               + (uint32_t)(8 * ct + lr) * 144
                               + (uint32_t)kt * 32 + (uint32_t)(sel & 1) * 16;
                uint32_t gh0, gh1, gl0, gl1;
                ldsm_x4(gaddr, gh0, gh1, gl0, gl1);
                mma_f16(y[0][ct], pa[0][kt][0], pa[0][kt][1], pa[0][kt][2], pa[0][kt][3], gh0, gh1);
                mma_f16(y[0][ct], pa[0][kt][0], pa[0][kt][1], pa[0][kt][2], pa[0][kt][3], gl0, gl1);
                mma_f16(y[1][ct], pa[1][kt][0], pa[1][kt][1], pa[1][kt][2], pa[1][kt][3], gh0, gh1);
                mma_f16(y[1][ct], pa[1][kt][0], pa[1][kt][1], pa[1][kt][2], pa[1][kt][3], gl0, gl1);
            }
        }
        __syncthreads();  // protect stage for next iter
    }

    // ---- rowsum reduce + normalize + transpose + write ----
    float* lsm = (float*)(smc + AT_LRED);  // 128 floats
#pragma unroll
    for (int i = 0; i < 2; i++)
#pragma unroll
        for (int hh = 0; hh < 2; hh++) {
            float v = l[i][hh];
            v += __shfl_xor_sync(0xffffffffu, v, 1);
            v += __shfl_xor_sync(0xffffffffu, v, 2);
            l[i][hh] = v;
        }
    if (tig == 0) {
        lsm[32 * wid + 0  + gid] = l[0][0];
        lsm[32 * wid + 8  + gid] = l[0][1];
        lsm[32 * wid + 16 + gid] = l[1][0];
        lsm[32 * wid + 24 + gid] = l[1][1];
    }
    __syncthreads();  // lsm ready; also: all warps done with stage smem
    float inv[2][2];
#pragma unroll
    for (int i = 0; i < 2; i++) {
        inv[i][0] = 1.f / lsm[32 * wid + 16 * i + gid];
        inv[i][1] = 1.f / lsm[32 * wid + 16 * i + 8 + gid];
    }

    float* ysm = (float*)smc;  // [128 c][pitch 132] floats (overwrites theta/stage0)
#pragma unroll
    for (int i = 0; i < 2; i++) {
        const int row0 = 32 * wid + 16 * i + gid, row1 = row0 + 8;
#pragma unroll
        for (int ct = 0; ct < 16; ct++) {
            int c = 8 * ct + 2 * tig;
            ysm[(c + 0) * 132 + row0] = y[i][ct][0] * inv[i][0];
            ysm[(c + 1) * 132 + row0] = y[i][ct][1] * inv[i][0];
            ysm[(c + 0) * 132 + row1] = y[i][ct][2] * inv[i][1];
            ysm[(c + 1) * 132 + row1] = y[i][ct][3] * inv[i][1];
        }
    }
    __syncthreads();
    for (int idx = tid; idx < 128 * 128; idx += 128) {
        int c = idx >> 7, n = idx & 127;
        d_y[(size_t)(b * CI + c) * N + n0 + n] = ysm[c * 132 + n];
    }
}

// ============================================================================
// K3: W_y = w_out @ y + b_out + deterministic BN partials. grid (4,32,4), 256.
// ============================================================================
__global__ void wy_kernel(const float* __restrict__ w_out, const float* __restrict__ b_out)
{
    __shared__ float Ws[32][65];
    __shared__ float Ys[32][128];
    const int b  = blockIdx.z;
    const int n0 = blockIdx.y * 128;
    const int o0 = blockIdx.x * 64;
    const int tid = threadIdx.x;
    const int tx = tid & 15, ty = tid >> 4;

    float acc[4][8];
#pragma unroll
    for (int i = 0; i < 4; i++)
#pragma unroll
        for (int j = 0; j < 8; j++) acc[i][j] = 0.f;

    for (int kc = 0; kc < CI; kc += 32) {
        for (int idx = tid; idx < 64 * 32; idx += 256) {
            int o = idx >> 5, k = idx & 31;
            Ws[k][o] = w_out[(o0 + o) * CI + kc + k];
        }
        for (int idx = tid; idx < 32 * 128; idx += 256) {
            int k = idx >> 7, n = idx & 127;
            Ys[k][n] = d_y[(size_t)(b * CI + kc + k) * N + n0 + n];
        }
        __syncthreads();
#pragma unroll 4
        for (int k = 0; k < 32; k++) {
            float a0 = Ws[k][ty * 4 + 0], a1 = Ws[k][ty * 4 + 1];
            float a2 = Ws[k][ty * 4 + 2], a3 = Ws[k][ty * 4 + 3];
            const float4 v0 = *(const float4*)&Ys[k][tx * 8];
            const float4 v1 = *(const float4*)&Ys[k][tx * 8 + 4];
            float bv[8] = {v0.x, v0.y, v0.z, v0.w, v1.x, v1.y, v1.z, v1.w};
#pragma unroll
            for (int j = 0; j < 8; j++) {
                acc[0][j] += a0 * bv[j];
                acc[1][j] += a1 * bv[j];
                acc[2][j] += a2 * bv[j];
                acc[3][j] += a3 * bv[j];
            }
        }
        __syncthreads();
    }

#pragma unroll
    for (int i = 0; i < 4; i++) {
        int oc = o0 + ty * 4 + i;
        float bb = b_out[oc];
        float s = 0.f, q = 0.f;
        float* p = d_wy + (size_t)(b * C + oc) * N + n0 + tx * 8;
#pragma unroll
        for (int j = 0; j < 8; j++) {
            float vv = acc[i][j] + bb;
            p[j] = vv;
            s += vv;
            q += vv * vv;
        }
#pragma unroll
        for (int off = 1; off < 16; off <<= 1) {
            s += __shfl_xor_sync(0xffffffffu, s, off);
            q += __shfl_xor_sync(0xffffffffu, q, off);
        }
        if (tx == 0) {
            int part = b * 32 + blockIdx.y;
            d_psum[oc * 128 + part] = s;
            d_psq[oc * 128 + part]  = q;
        }
    }
}

// ============================================================================
// K4: reduce BN partials. grid 256, 32 threads.
// ============================================================================
__global__ void bnstat_kernel(const float* __restrict__ gamma, const float* __restrict__ beta)
{
    int c = blockIdx.x, t = threadIdx.x;
    float s = 0.f, q = 0.f;
#pragma unroll
    for (int p = t; p < 128; p += 32) {
        s += d_psum[c * 128 + p];
        q += d_psq[c * 128 + p];
    }
#pragma unroll
    for (int off = 1; off < 32; off <<= 1) {
        s += __shfl_xor_sync(0xffffffffu, s, off);
        q += __shfl_xor_sync(0xffffffffu, q, off);
    }
    if (t == 0) {
        const float invn = 1.f / 16384.f;
        float mean = s * invn;
        float var  = q * invn - mean * mean;
        float sc   = gamma[c] * rsqrtf(var + 1e-5f);
        d_bnA[c] = sc;
        d_bnB[c] = beta[c] - mean * sc;
    }
}

// ============================================================================
// K5: out = W_y * scale[c] + shift[c] + x
// ============================================================================
__global__ void bnadd_kernel(const float* __restrict__ x, float* __restrict__ out)
{
    int idx4 = blockIdx.x * blockDim.x + threadIdx.x;
    if (idx4 >= B * C * N / 4) return;
    int c = (idx4 >> 10) & (C - 1);
    float sc = d_bnA[c], bb = d_bnB[c];
    float4 w  = ((const float4*)d_wy)[idx4];
    float4 xv = ((const float4*)x)[idx4];
    float4 r;
    r.x = w.x * sc + bb + xv.x;
    r.y = w.y * sc + bb + xv.y;
    r.z = w.z * sc + bb + xv.z;
    r.w = w.w * sc + bb + xv.w;
    ((float4*)out)[idx4] = r;
}

// ============================================================================
extern "C" void kernel_launch(void* const* d_in, const int* in_sizes, int n_in,
                              void* d_out, int out_size)
{
    const float* x     = (const float*)d_in[0];
    const float* w_g   = (const float*)d_in[1];
    const float* b_g   = (const float*)d_in[2];
    const float* w_t   = (const float*)d_in[3];
    const float* b_t   = (const float*)d_in[4];
    const float* w_p   = (const float*)d_in[5];
    const float* b_p   = (const float*)d_in[6];
    const float* w_o   = (const float*)d_in[7];
    const float* b_o   = (const float*)d_in[8];
    const float* gamma = (const float*)d_in[9];
    const float* beta  = (const float*)d_in[10];
    float* out = (float*)d_out;

    cudaFuncSetAttribute(proj_kernel, cudaFuncAttributeMaxDynamicSharedMemorySize, PROJ_SMEM);
    cudaFuncSetAttribute(attn_kernel, cudaFuncAttributeMaxDynamicSharedMemorySize, ATTN_SMEM);

    splitw_kernel<<<384, 256>>>(w_g, w_t, w_p);
    splitx_kernel<<<4096, 256>>>(x);
    proj_kernel<<<dim3(3, 32, 4), 256, PROJ_SMEM>>>(b_g, b_t, b_p);
    attn_kernel<<<dim3(32, 4), 128, ATTN_SMEM>>>();
    wy_kernel<<<dim3(4, 32, 4), 256>>>(w_o, b_o);
    bnstat_kernel<<<256, 32>>>(gamma, beta);
    bnadd_kernel<<<4096, 256>>>(x, out);
}

// round 15
// speedup vs baseline: 1.0546x; 1.0546x over previous
#include <cuda_runtime.h>
#include <cuda_bf16.h>
#include <cuda_fp16.h>
#include <cstdint>

// NonlocalBlock: B=4, C=256, Ci=128, H=W=64 (N=4096)
// out = BN(w_out @ softmax(theta^T phi) @ g^T) + x
// Proj: HMMA bf16 3-chain -> fp16 operand planes.
// Attn: HMMA fp16 2-chain, 8 warps; warp (rg,h): QK rows 32rg..+31 x m-half h,
// P (hi fp16) via smem, PV rows x c-half h over full m.
// R15 = R14 with the smem overflow fixed (lred needs 1024B; 197120 -> 197632).

namespace {
constexpr int B  = 4;
constexpr int C  = 256;
constexpr int CI = 128;
constexpr int N  = 4096;
}

// ---- scratch (static device globals; no runtime allocation allowed) ----
__device__ float d_y[B * CI * N];
__device__ float d_wy[B * C * N];
__device__ float d_psum[C * 128];
__device__ float d_psq[C * 128];
__device__ float d_bnA[C];
__device__ float d_bnB[C];
// fp16 attention operands
__device__ alignas(16) __half d_thT[B * N * CI];      // [b][n][ci]  hi only
__device__ alignas(16) __half d_phT_hi[B * N * CI];   // [b][m][ci]
__device__ alignas(16) __half d_phT_lo[B * N * CI];
__device__ alignas(16) __half d_g16_hi[B * CI * N];   // [b][c][m]
__device__ alignas(16) __half d_g16_lo[B * CI * N];
// bf16 split inputs for HMMA proj
__device__ alignas(16) __nv_bfloat16 d_W_hi[384 * 256];
__device__ alignas(16) __nv_bfloat16 d_W_lo[384 * 256];
__device__ alignas(16) __nv_bfloat16 d_x_hi[B * C * N];   // [b][c][n]
__device__ alignas(16) __nv_bfloat16 d_x_lo[B * C * N];

// ============================================================================
// helpers
// ============================================================================
__device__ __forceinline__ uint32_t smem_u32(const void* p) {
    uint32_t a;
    asm("{ .reg .u64 t; cvta.to.shared.u64 t, %1; cvt.u32.u64 %0, t; }" : "=r"(a) : "l"(p));
    return a;
}
__device__ __forceinline__ uint16_t f2bf(float v) {
    return __bfloat16_as_ushort(__float2bfloat16(v));
}
__device__ __forceinline__ float bf2f(uint16_t u) {
    return __bfloat162float(__ushort_as_bfloat16(u));
}
__device__ __forceinline__ uint16_t f2h(float v) {
    return __half_as_ushort(__float2half_rn(v));
}
__device__ __forceinline__ float h2f(uint16_t u) {
    return __half2float(__ushort_as_half(u));
}
__device__ __forceinline__ uint32_t pack2(uint16_t lo, uint16_t hi) {
    return (uint32_t)lo | ((uint32_t)hi << 16);
}
__device__ __forceinline__ uint32_t f16x2(float lo, float hi) {
    __half2 h = __floats2half2_rn(lo, hi);
    return *reinterpret_cast<uint32_t*>(&h);
}
__device__ __forceinline__ void mma_bf16(float* c,
                                         uint32_t a0, uint32_t a1, uint32_t a2, uint32_t a3,
                                         uint32_t b0, uint32_t b1) {
    asm volatile(
        "mma.sync.aligned.m16n8k16.row.col.f32.bf16.bf16.f32 "
        "{%0,%1,%2,%3}, {%4,%5,%6,%7}, {%8,%9}, {%0,%1,%2,%3};"
        : "+f"(c[0]), "+f"(c[1]), "+f"(c[2]), "+f"(c[3])
        : "r"(a0), "r"(a1), "r"(a2), "r"(a3), "r"(b0), "r"(b1));
}
__device__ __forceinline__ void mma_f16(float* c,
                                        uint32_t a0, uint32_t a1, uint32_t a2, uint32_t a3,
                                        uint32_t b0, uint32_t b1) {
    asm volatile(
        "mma.sync.aligned.m16n8k16.row.col.f32.f16.f16.f32 "
        "{%0,%1,%2,%3}, {%4,%5,%6,%7}, {%8,%9}, {%0,%1,%2,%3};"
        : "+f"(c[0]), "+f"(c[1]), "+f"(c[2]), "+f"(c[3])
        : "r"(a0), "r"(a1), "r"(a2), "r"(a3), "r"(b0), "r"(b1));
}
__device__ __forceinline__ void ldsm_x4(uint32_t addr, uint32_t& r0, uint32_t& r1,
                                        uint32_t& r2, uint32_t& r3) {
    asm volatile("ldmatrix.sync.aligned.m8n8.x4.shared.b16 {%0,%1,%2,%3}, [%4];"
                 : "=r"(r0), "=r"(r1), "=r"(r2), "=r"(r3) : "r"(addr));
}
__device__ __forceinline__ void ldsm_x4_t(uint32_t addr, uint32_t& r0, uint32_t& r1,
                                          uint32_t& r2, uint32_t& r3) {
    asm volatile("ldmatrix.sync.aligned.m8n8.x4.trans.shared.b16 {%0,%1,%2,%3}, [%4];"
                 : "=r"(r0), "=r"(r1), "=r"(r2), "=r"(r3) : "r"(addr));
}
__device__ __forceinline__ void cp16(uint32_t saddr, const void* gaddr) {
    asm volatile("cp.async.cg.shared.global [%0], [%1], 16;" :: "r"(saddr), "l"(gaddr));
}
__device__ __forceinline__ void sts32(uint32_t addr, uint32_t v) {
    asm volatile("st.shared.u32 [%0], %1;" :: "r"(addr), "r"(v) : "memory");
}
#define CP_COMMIT() asm volatile("cp.async.commit_group;" ::: "memory")
#define CP_WAIT(n)  asm volatile("cp.async.wait_group %0;" :: "n"(n) : "memory")

// ============================================================================
// K0a: split weights. grid 384 x 256.
// ============================================================================
__global__ void splitw_kernel(const float* __restrict__ w_g,
                              const float* __restrict__ w_t,
                              const float* __restrict__ w_p)
{
    int row = blockIdx.x, t = threadIdx.x;
    const float* src = (row < 128) ? w_g + (size_t)row * 256
                     : (row < 256) ? w_t + (size_t)(row - 128) * 256
                                   : w_p + (size_t)(row - 256) * 256;
    float v = src[t];
    uint16_t h = f2bf(v);
    d_W_hi[(size_t)row * 256 + t] = __ushort_as_bfloat16(h);
    d_W_lo[(size_t)row * 256 + t] = __ushort_as_bfloat16(f2bf(v - bf2f(h)));
}

// ============================================================================
// K0b: split x. grid 4096 x 256.
// ============================================================================
__global__ void splitx_kernel(const float* __restrict__ x)
{
    int idx4 = blockIdx.x * blockDim.x + threadIdx.x;
    float4 v = ((const float4*)x)[idx4];
    uint16_t h0 = f2bf(v.x), h1 = f2bf(v.y), h2 = f2bf(v.z), h3 = f2bf(v.w);
    *(uint2*)(d_x_hi + (size_t)idx4 * 4) = make_uint2(pack2(h0, h1), pack2(h2, h3));
    *(uint2*)(d_x_lo + (size_t)idx4 * 4) =
        make_uint2(pack2(f2bf(v.x - bf2f(h0)), f2bf(v.y - bf2f(h1))),
                   pack2(f2bf(v.z - bf2f(h2)), f2bf(v.w - bf2f(h3))));
}

// ============================================================================
// K1: HMMA projection GEMM (bf16 3-chain, fp16 outputs). grid (3,32,4), 256.
// mt: 0 -> g16 [b][c][m] hi+lo; 1 -> thT [b][n][ci] hi only; 2 -> phT hi+lo
// ============================================================================
#define PJ_WHI   0u
#define PJ_WLO   10240u
#define PJ_XHI   20480u
#define PJ_XLO   29184u
#define PJ_STAGE 37888u
#define PROJ_SMEM 75776

__global__ void __launch_bounds__(256, 2) proj_kernel(const float* __restrict__ b_g,
                                                      const float* __restrict__ b_t,
                                                      const float* __restrict__ b_p)
{
    extern __shared__ char smc[];
    const uint32_t sb = smem_u32(smc);
    const int mt = blockIdx.x;
    const int n0 = blockIdx.y * 128;
    const int b  = blockIdx.z;
    const int tid = threadIdx.x, wid = tid >> 5, lane = tid & 31;
    const int gid = lane >> 2, tig = lane & 3;
    const int obase = mt * 128;

    float acc[16][4];
#pragma unroll
    for (int nf = 0; nf < 16; nf++)
#pragma unroll
        for (int e = 0; e < 4; e++) acc[nf][e] = 0.f;

    auto load_chunk = [&](int st, int kc) {
        uint32_t base = sb + (uint32_t)st * PJ_STAGE;
        for (int idx = tid; idx < 512; idx += 256) {
            int r = idx >> 2, sg = idx & 3;
            cp16(base + PJ_WHI + (uint32_t)r * 80 + sg * 16,
                 d_W_hi + (size_t)(obase + r) * 256 + kc + sg * 8);
            cp16(base + PJ_WLO + (uint32_t)r * 80 + sg * 16,
                 d_W_lo + (size_t)(obase + r) * 256 + kc + sg * 8);
            int xr = idx >> 4, xs = idx & 15;
            cp16(base + PJ_XHI + (uint32_t)xr * 272 + xs * 16,
                 d_x_hi + (size_t)(b * C + kc + xr) * N + n0 + xs * 8);
            cp16(base + PJ_XLO + (uint32_t)xr * 272 + xs * 16,
                 d_x_lo + (size_t)(b * C + kc + xr) * N + n0 + xs * 8);
        }
    };

    load_chunk(0, 0);
    CP_COMMIT();
    for (int c = 0; c < 8; ++c) {
        if (c + 1 < 8) { load_chunk((c + 1) & 1, (c + 1) * 32); CP_COMMIT(); CP_WAIT(1); }
        else           { CP_WAIT(0); }
        __syncthreads();
        uint32_t base = sb + (uint32_t)(c & 1) * PJ_STAGE;
#pragma unroll
        for (int kk = 0; kk < 2; ++kk) {
            uint32_t aaddr = base + PJ_WHI + (uint32_t)(wid * 16 + (lane & 15)) * 80
                           + (uint32_t)(lane >> 4) * 16 + (uint32_t)kk * 32;
            uint32_t ah0, ah1, ah2, ah3, al0, al1, al2, al3;
            ldsm_x4(aaddr, ah0, ah1, ah2, ah3);
            ldsm_x4(aaddr + (PJ_WLO - PJ_WHI), al0, al1, al2, al3);
#pragma unroll
            for (int nf = 0; nf < 16; ++nf) {
                uint32_t baddr = base + PJ_XHI
                               + (uint32_t)(kk * 16 + ((lane >> 3) & 1) * 8 + (lane & 7)) * 272
                               + (uint32_t)(lane >> 4) * (PJ_XLO - PJ_XHI)
                               + (uint32_t)nf * 16;
                uint32_t bh0, bh1, bl0, bl1;
                ldsm_x4_t(baddr, bh0, bh1, bl0, bl1);
                mma_bf16(acc[nf], ah0, ah1, ah2, ah3, bh0, bh1);
                mma_bf16(acc[nf], ah0, ah1, ah2, ah3, bl0, bl1);
                mma_bf16(acc[nf], al0, al1, al2, al3, bh0, bh1);
            }
        }
        __syncthreads();
    }

    const float* bias = (mt == 0) ? b_g : (mt == 1) ? b_t : b_p;
    const int r0 = wid * 16 + gid, r1 = r0 + 8;
    const float br0 = bias[r0], br1 = bias[r1];
#pragma unroll
    for (int nf = 0; nf < 16; ++nf) {
        acc[nf][0] += br0; acc[nf][1] += br0;
        acc[nf][2] += br1; acc[nf][3] += br1;
    }

    if (mt == 0) {
        __half* dsts[2] = { d_g16_hi + (size_t)(b * CI) * N + n0,
                            d_g16_lo + (size_t)(b * CI) * N + n0 };
#pragma unroll
        for (int rnd = 0; rnd < 2; ++rnd) {
#pragma unroll
            for (int nf = 0; nf < 16; ++nf) {
                int ncol = 8 * nf + 2 * tig;
                uint16_t h0 = f2h(acc[nf][0]), h1 = f2h(acc[nf][1]);
                uint16_t h2 = f2h(acc[nf][2]), h3 = f2h(acc[nf][3]);
                uint32_t v0, v1;
                if (rnd == 0) { v0 = pack2(h0, h1); v1 = pack2(h2, h3); }
                else {
                    v0 = pack2(f2h(acc[nf][0] - h2f(h0)), f2h(acc[nf][1] - h2f(h1)));
                    v1 = pack2(f2h(acc[nf][2] - h2f(h2)), f2h(acc[nf][3] - h2f(h3)));
                }
                *(uint32_t*)(smc + (uint32_t)r0 * 272 + (uint32_t)ncol * 2) = v0;
                *(uint32_t*)(smc + (uint32_t)r1 * 272 + (uint32_t)ncol * 2) = v1;
            }
            __syncthreads();
            for (int idx = tid; idx < 2048; idx += 256) {
                int row = idx >> 4, c16 = idx & 15;
                *(uint4*)(dsts[rnd] + (size_t)row * N + c16 * 8) =
                    *(const uint4*)(smc + (uint32_t)row * 272 + (uint32_t)c16 * 16);
            }
            __syncthreads();
        }
    } else if (mt == 1) {
        __half* dst = d_thT;
#pragma unroll
        for (int nf = 0; nf < 16; ++nf) {
            int nc = 8 * nf + 2 * tig;
            *(uint16_t*)(smc + (uint32_t)(nc + 0) * 272 + (uint32_t)r0 * 2) = f2h(acc[nf][0]);
            *(uint16_t*)(smc + (uint32_t)(nc + 1) * 272 + (uint32_t)r0 * 2) = f2h(acc[nf][1]);
            *(uint16_t*)(smc + (uint32_t)(nc + 0) * 272 + (uint32_t)r1 * 2) = f2h(acc[nf][2]);
            *(uint16_t*)(smc + (uint32_t)(nc + 1) * 272 + (uint32_t)r1 * 2) = f2h(acc[nf][3]);
        }
        __syncthreads();
        for (int idx = tid; idx < 2048; idx += 256) {
            int row = idx >> 4, c16 = idx & 15;
            *(uint4*)(dst + (size_t)(b * N + n0 + row) * CI + c16 * 8) =
                *(const uint4*)(smc + (uint32_t)row * 272 + (uint32_t)c16 * 16);
        }
        __syncthreads();
    } else {
        __half* dsts[2] = { d_phT_hi, d_phT_lo };
#pragma unroll
        for (int rnd = 0; rnd < 2; ++rnd) {
#pragma unroll
            for (int nf = 0; nf < 16; ++nf) {
                int nc = 8 * nf + 2 * tig;
                uint16_t h0 = f2h(acc[nf][0]), h1 = f2h(acc[nf][1]);
                uint16_t h2 = f2h(acc[nf][2]), h3 = f2h(acc[nf][3]);
                uint16_t v0, v1, v2, v3;
                if (rnd == 0) { v0 = h0; v1 = h1; v2 = h2; v3 = h3; }
                else {
                    v0 = f2h(acc[nf][0] - h2f(h0)); v1 = f2h(acc[nf][1] - h2f(h1));
                    v2 = f2h(acc[nf][2] - h2f(h2)); v3 = f2h(acc[nf][3] - h2f(h3));
                }
                *(uint16_t*)(smc + (uint32_t)(nc + 0) * 272 + (uint32_t)r0 * 2) = v0;
                *(uint16_t*)(smc + (uint32_t)(nc + 1) * 272 + (uint32_t)r0 * 2) = v1;
                *(uint16_t*)(smc + (uint32_t)(nc + 0) * 272 + (uint32_t)r1 * 2) = v2;
                *(uint16_t*)(smc + (uint32_t)(nc + 1) * 272 + (uint32_t)r1 * 2) = v3;
            }
            __syncthreads();
            for (int idx = tid; idx < 2048; idx += 256) {
                int row = idx >> 4, c16 = idx & 15;
                *(uint4*)(dsts[rnd] + (size_t)(b * N + n0 + row) * CI + c16 * 8) =
                    *(const uint4*)(smc + (uint32_t)row * 272 + (uint32_t)c16 * 16);
            }
            __syncthreads();
        }
    }
}

// ============================================================================
// K2: HMMA fp16 flash attention. 256 thr / 8 warps; warp (rg, h):
//   QK : S[32 rows][m-half 32], 2 chains; exp; P hi fp16 -> smem
//   PV : Y[32 rows][c-half 64] over FULL m, 2 chains
// grid (32, 4), dyn smem 197632 B (R14 had 197120 -> lred overflow -> IMA).
// SMEM: TH 34816 | 2 st x (PHI 2x17408 + G 2x18432) = 143360 | P 18432 | lred 1024
//       34816 + 143360 = 178176 (AT_P); 178176+18432 = 196608 (AT_LRED); +1024 = 197632
// ============================================================================
#define AT_TH      0u
#define AT_ST      34816u
#define ST_PHI_HI  0u
#define ST_PHI_LO  17408u
#define ST_G_HI    34816u
#define ST_G_LO    53248u
#define AT_STAGE   71680u
#define AT_P       178176u
#define AT_LRED    196608u
#define ATTN_SMEM  197632

__global__ void __launch_bounds__(256, 1) attn_kernel()
{
    extern __shared__ char smc[];
    const uint32_t sb = smem_u32(smc);
    const int b   = blockIdx.y;
    const int n0  = blockIdx.x * 128;
    const int tid = threadIdx.x;
    const int wid = tid >> 5, lane = tid & 31;
    const int gid = lane >> 2, tig = lane & 3;
    const int sel = lane >> 3, lr = lane & 7;
    const int rg = wid >> 1, h = wid & 1;

    // ---- theta hi tile -> smem once ----
    {
        const __half* th = d_thT + (size_t)(b * N + n0) * CI;
        for (int idx = tid; idx < 128 * 16; idx += 256) {
            int r = idx >> 4, ch = idx & 15;
            cp16(sb + AT_TH + (uint32_t)r * 272 + (uint32_t)ch * 16,
                 th + (size_t)r * CI + ch * 8);
        }
    }
    CP_COMMIT();

    auto stage_load = [&](int st, int it) {
        const int m0 = it * 64;
        uint32_t base = sb + AT_ST + (uint32_t)st * AT_STAGE;
        const __half* ph = d_phT_hi + (size_t)(b * N + m0) * CI;
        const __half* pl = d_phT_lo + (size_t)(b * N + m0) * CI;
        for (int idx = tid; idx < 64 * 16; idx += 256) {
            int r = idx >> 4, ch = idx & 15;
            uint32_t o = (uint32_t)r * 272 + (uint32_t)ch * 16;
            cp16(base + ST_PHI_HI + o, ph + (size_t)r * CI + ch * 8);
            cp16(base + ST_PHI_LO + o, pl + (size_t)r * CI + ch * 8);
        }
        const __half* gh = d_g16_hi + (size_t)b * CI * N + m0;
        const __half* gl = d_g16_lo + (size_t)b * CI * N + m0;
        for (int idx = tid; idx < 128 * 8; idx += 256) {
            int r = idx >> 3, ch = idx & 7;
            uint32_t o = (uint32_t)r * 144 + (uint32_t)ch * 16;
            cp16(base + ST_G_HI + o, gh + (size_t)r * N + ch * 8);
            cp16(base + ST_G_LO + o, gl + (size_t)r * N + ch * 8);
        }
    };

    stage_load(0, 0);
    CP_COMMIT();

    float y[2][8][4];
#pragma unroll
    for (int i = 0; i < 2; i++)
#pragma unroll
        for (int ct = 0; ct < 8; ct++)
#pragma unroll
            for (int e = 0; e < 4; e++) y[i][ct][e] = 0.f;
    float l[2][2] = {{0.f, 0.f}, {0.f, 0.f}};

    // theta A-frag bases (rows 32*rg + 16*i + (lane&15))
    const uint32_t a0_base = sb + AT_TH + (uint32_t)(32 * rg + (lane & 15)) * 272
                           + (uint32_t)(lane >> 4) * 16;
    const uint32_t a1_base = a0_base + 16u * 272u;
    // P A-frag bases (same rows, 144B pitch)
    const uint32_t p0_base = sb + AT_P + (uint32_t)(32 * rg + (lane & 15)) * 144
                           + (uint32_t)(lane >> 4) * 16;
    const uint32_t p1_base = p0_base + 16u * 144u;

    for (int it = 0; it < 64; ++it) {
        if (it + 1 < 64) { stage_load((it + 1) & 1, it + 1); CP_COMMIT(); CP_WAIT(1); }
        else             { CP_WAIT(0); }
        __syncthreads();  // B1: stage ready; prior PV done reading P
        const uint32_t stb = sb + AT_ST + (uint32_t)(it & 1) * AT_STAGE;

        // ---- QK: S[32 x 32] (m-half h) ----
        float s[2][4][4];
#pragma unroll
        for (int i = 0; i < 2; i++)
#pragma unroll
            for (int j = 0; j < 4; j++)
#pragma unroll
                for (int e = 0; e < 4; e++) s[i][j][e] = 0.f;

#pragma unroll
        for (int k = 0; k < 8; k++) {
            uint32_t A00, A01, A02, A03, A10, A11, A12, A13;
            ldsm_x4(a0_base + (uint32_t)k * 32, A00, A01, A02, A03);
            ldsm_x4(a1_base + (uint32_t)k * 32, A10, A11, A12, A13);
#pragma unroll
            for (int j = 0; j < 4; j++) {
                uint32_t baddr = stb + ((sel >= 2) ? ST_PHI_LO : ST_PHI_HI)
                               + (uint32_t)(32 * h + 8 * j + lr) * 272
                               + (uint32_t)k * 32 + (uint32_t)(sel & 1) * 16;
                uint32_t bh0, bh1, bl0, bl1;
                ldsm_x4(baddr, bh0, bh1, bl0, bl1);
                mma_f16(s[0][j], A00, A01, A02, A03, bh0, bh1);
                mma_f16(s[0][j], A00, A01, A02, A03, bl0, bl1);
                mma_f16(s[1][j], A10, A11, A12, A13, bh0, bh1);
                mma_f16(s[1][j], A10, A11, A12, A13, bl0, bl1);
            }
        }

        // ---- exp + rowsums + P (hi fp16) -> smem ----
#pragma unroll
        for (int i = 0; i < 2; i++) {
            const int row0 = 32 * rg + 16 * i + gid, row1 = row0 + 8;
#pragma unroll
            for (int j = 0; j < 4; j++) {
#pragma unroll
                for (int e = 0; e < 4; e++) s[i][j][e] = __expf(s[i][j][e]);
                l[i][0] += s[i][j][0] + s[i][j][1];
                l[i][1] += s[i][j][2] + s[i][j][3];
                uint32_t mcol2 = (uint32_t)(32 * h + 8 * j + 2 * tig) * 2;
                sts32(sb + AT_P + (uint32_t)row0 * 144 + mcol2, f16x2(s[i][j][0], s[i][j][1]));
                sts32(sb + AT_P + (uint32_t)row1 * 144 + mcol2, f16x2(s[i][j][2], s[i][j][3]));
            }
        }
        __syncthreads();  // B2: P visible to partner warps

        // ---- PV: Y[32 x 64] (c-half h) over full m ----
#pragma unroll
        for (int kt = 0; kt < 4; kt++) {
            uint32_t P00, P01, P02, P03, P10, P11, P12, P13;
            ldsm_x4(p0_base + (uint32_t)kt * 32, P00, P01, P02, P03);
            ldsm_x4(p1_base + (uint32_t)kt * 32, P10, P11, P12, P13);
#pragma unroll
            for (int ct = 0; ct < 8; ct++) {
                uint32_t gaddr = stb + ((sel >= 2) ? ST_G_LO : ST_G_HI)
                               + (uint32_t)(64 * h + 8 * ct + lr) * 144
                               + (uint32_t)kt * 32 + (uint32_t)(sel & 1) * 16;
                uint32_t gh0, gh1, gl0, gl1;
                ldsm_x4(gaddr, gh0, gh1, gl0, gl1);
                mma_f16(y[0][ct], P00, P01, P02, P03, gh0, gh1);
                mma_f16(y[0][ct], P00, P01, P02, P03, gl0, gl1);
                mma_f16(y[1][ct], P10, P11, P12, P13, gh0, gh1);
                mma_f16(y[1][ct], P10, P11, P12, P13, gl0, gl1);
            }
        }
        __syncthreads();  // B3: PV reads (stage, P) done before next writes
    }

    // ---- rowsum reduce across m-half pair + normalize + transpose + write ----
    float* lsm = (float*)(smc + AT_LRED);  // [2][128] = 1024 B, in bounds now
#pragma unroll
    for (int i = 0; i < 2; i++)
#pragma unroll
        for (int hh = 0; hh < 2; hh++) {
            float v = l[i][hh];
            v += __shfl_xor_sync(0xffffffffu, v, 1);
            v += __shfl_xor_sync(0xffffffffu, v, 2);
            l[i][hh] = v;
        }
    if (tig == 0) {
#pragma unroll
        for (int i = 0; i < 2; i++) {
            lsm[h * 128 + 32 * rg + 16 * i + gid]     = l[i][0];
            lsm[h * 128 + 32 * rg + 16 * i + 8 + gid] = l[i][1];
        }
    }
    __syncthreads();
    float inv[2][2];
#pragma unroll
    for (int i = 0; i < 2; i++) {
        int r0i = 32 * rg + 16 * i + gid;
        inv[i][0] = 1.f / (lsm[r0i] + lsm[128 + r0i]);
        inv[i][1] = 1.f / (lsm[r0i + 8] + lsm[128 + r0i + 8]);
    }

    float* ysm = (float*)smc;  // [128 c][pitch 132] floats (overlays theta/stage0)
    __syncthreads();
#pragma unroll
    for (int i = 0; i < 2; i++) {
        const int row0 = 32 * rg + 16 * i + gid, row1 = row0 + 8;
#pragma unroll
        for (int ct = 0; ct < 8; ct++) {
            int c = 64 * h + 8 * ct + 2 * tig;
            ysm[(c + 0) * 132 + row0] = y[i][ct][0] * inv[i][0];
            ysm[(c + 1) * 132 + row0] = y[i][ct][1] * inv[i][0];
            ysm[(c + 0) * 132 + row1] = y[i][ct][2] * inv[i][1];
            ysm[(c + 1) * 132 + row1] = y[i][ct][3] * inv[i][1];
        }
    }
    __syncthreads();
    for (int idx = tid; idx < 128 * 128; idx += 256) {
        int c = idx >> 7, n = idx & 127;
        d_y[(size_t)(b * CI + c) * N + n0 + n] = ysm[c * 132 + n];
    }
}

// ============================================================================
// K3: W_y = w_out @ y + b_out + deterministic BN partials. grid (4,32,4), 256.
// ============================================================================
__global__ void wy_kernel(const float* __restrict__ w_out, const float* __restrict__ b_out)
{
    __shared__ float Ws[32][65];
    __shared__ float Ys[32][128];
    const int b  = blockIdx.z;
    const int n0 = blockIdx.y * 128;
    const int o0 = blockIdx.x * 64;
    const int tid = threadIdx.x;
    const int tx = tid & 15, ty = tid >> 4;

    float acc[4][8];
#pragma unroll
    for (int i = 0; i < 4; i++)
#pragma unroll
        for (int j = 0; j < 8; j++) acc[i][j] = 0.f;

    for (int kc = 0; kc < CI; kc += 32) {
        for (int idx = tid; idx < 64 * 32; idx += 256) {
            int o = idx >> 5, k = idx & 31;
            Ws[k][o] = w_out[(o0 + o) * CI + kc + k];
        }
        for (int idx = tid; idx < 32 * 128; idx += 256) {
            int k = idx >> 7, n = idx & 127;
            Ys[k][n] = d_y[(size_t)(b * CI + kc + k) * N + n0 + n];
        }
        __syncthreads();
#pragma unroll 4
        for (int k = 0; k < 32; k++) {
            float a0 = Ws[k][ty * 4 + 0], a1 = Ws[k][ty * 4 + 1];
            float a2 = Ws[k][ty * 4 + 2], a3 = Ws[k][ty * 4 + 3];
            const float4 v0 = *(const float4*)&Ys[k][tx * 8];
            const float4 v1 = *(const float4*)&Ys[k][tx * 8 + 4];
            float bv[8] = {v0.x, v0.y, v0.z, v0.w, v1.x, v1.y, v1.z, v1.w};
#pragma unroll
            for (int j = 0; j < 8; j++) {
                acc[0][j] += a0 * bv[j];
                acc[1][j] += a1 * bv[j];
                acc[2][j] += a2 * bv[j];
                acc[3][j] += a3 * bv[j];
            }
        }
        __syncthreads();
    }

#pragma unroll
    for (int i = 0; i < 4; i++) {
        int oc = o0 + ty * 4 + i;
        float bb = b_out[oc];
        float s = 0.f, q = 0.f;
        float* p = d_wy + (size_t)(b * C + oc) * N + n0 + tx * 8;
#pragma unroll
        for (int j = 0; j < 8; j++) {
            float vv = acc[i][j] + bb;
            p[j] = vv;
            s += vv;
            q += vv * vv;
        }
#pragma unroll
        for (int off = 1; off < 16; off <<= 1) {
            s += __shfl_xor_sync(0xffffffffu, s, off);
            q += __shfl_xor_sync(0xffffffffu, q, off);
        }
        if (tx == 0) {
            int part = b * 32 + blockIdx.y;
            d_psum[oc * 128 + part] = s;
            d_psq[oc * 128 + part]  = q;
        }
    }
}

// ============================================================================
// K4: reduce BN partials. grid 256, 32 threads.
// ============================================================================
__global__ void bnstat_kernel(const float* __restrict__ gamma, const float* __restrict__ beta)
{
    int c = blockIdx.x, t = threadIdx.x;
    float s = 0.f, q = 0.f;
#pragma unroll
    for (int p = t; p < 128; p += 32) {
        s += d_psum[c * 128 + p];
        q += d_psq[c * 128 + p];
    }
#pragma unroll
    for (int off = 1; off < 32; off <<= 1) {
        s += __shfl_xor_sync(0xffffffffu, s, off);
        q += __shfl_xor_sync(0xffffffffu, q, off);
    }
    if (t == 0) {
        const float invn = 1.f / 16384.f;
        float mean = s * invn;
        float var  = q * invn - mean * mean;
        float sc   = gamma[c] * rsqrtf(var + 1e-5f);
        d_bnA[c] = sc;
        d_bnB[c] = beta[c] - mean * sc;
    }
}

// ============================================================================
// K5: out = W_y * scale[c] + shift[c] + x
// ============================================================================
__global__ void bnadd_kernel(const float* __restrict__ x, float* __restrict__ out)
{
    int idx4 = blockIdx.x * blockDim.x + threadIdx.x;
    if (idx4 >= B * C * N / 4) return;
    int c = (idx4 >> 10) & (C - 1);
    float sc = d_bnA[c], bb = d_bnB[c];
    float4 w  = ((const float4*)d_wy)[idx4];
    float4 xv = ((const float4*)x)[idx4];
    float4 r;
    r.x = w.x * sc + bb + xv.x;
    r.y = w.y * sc + bb + xv.y;
    r.z = w.z * sc + bb + xv.z;
    r.w = w.w * sc + bb + xv.w;
    ((float4*)out)[idx4] = r;
}

// ============================================================================
extern "C" void kernel_launch(void* const* d_in, const int* in_sizes, int n_in,
                              void* d_out, int out_size)
{
    const float* x     = (const float*)d_in[0];
    const float* w_g   = (const float*)d_in[1];
    const float* b_g   = (const float*)d_in[2];
    const float* w_t   = (const float*)d_in[3];
    const float* b_t   = (const float*)d_in[4];
    const float* w_p   = (const float*)d_in[5];
    const float* b_p   = (const float*)d_in[6];
    const float* w_o   = (const float*)d_in[7];
    const float* b_o   = (const float*)d_in[8];
    const float* gamma = (const float*)d_in[9];
    const float* beta  = (const float*)d_in[10];
    float* out = (float*)d_out;

    cudaFuncSetAttribute(proj_kernel, cudaFuncAttributeMaxDynamicSharedMemorySize, PROJ_SMEM);
    cudaFuncSetAttribute(attn_kernel, cudaFuncAttributeMaxDynamicSharedMemorySize, ATTN_SMEM);

    splitw_kernel<<<384, 256>>>(w_g, w_t, w_p);
    splitx_kernel<<<4096, 256>>>(x);
    proj_kernel<<<dim3(3, 32, 4), 256, PROJ_SMEM>>>(b_g, b_t, b_p);
    attn_kernel<<<dim3(32, 4), 256, ATTN_SMEM>>>();
    wy_kernel<<<dim3(4, 32, 4), 256>>>(w_o, b_o);
    bnstat_kernel<<<256, 32>>>(gamma, beta);
    bnadd_kernel<<<4096, 256>>>(x, out);
}

// round 16
// speedup vs baseline: 1.6373x; 1.5525x over previous
#include <cuda_runtime.h>
#include <cuda_bf16.h>
#include <cuda_fp16.h>
#include <cstdint>

// NonlocalBlock: B=4, C=256, Ci=128, H=W=64 (N=4096)
// out = BN(w_out @ softmax(theta^T phi) @ g^T) + x
// R16: attn = R11 structure (8 warps x 16 rows, theta in regs, P in regs,
// ONE barrier/iter) + fp16 2-chain arithmetic (validated rel_err ~3e-5).
// Proj: HMMA bf16 3-chain -> fp16 operand planes (theta hi-only).

namespace {
constexpr int B  = 4;
constexpr int C  = 256;
constexpr int CI = 128;
constexpr int N  = 4096;
}

// ---- scratch (static device globals; no runtime allocation allowed) ----
__device__ float d_y[B * CI * N];
__device__ float d_wy[B * C * N];
__device__ float d_psum[C * 128];
__device__ float d_psq[C * 128];
__device__ float d_bnA[C];
__device__ float d_bnB[C];
// fp16 attention operands
__device__ alignas(16) __half d_thT[B * N * CI];      // [b][n][ci]  hi only
__device__ alignas(16) __half d_phT_hi[B * N * CI];   // [b][m][ci]
__device__ alignas(16) __half d_phT_lo[B * N * CI];
__device__ alignas(16) __half d_g16_hi[B * CI * N];   // [b][c][m]
__device__ alignas(16) __half d_g16_lo[B * CI * N];
// bf16 split inputs for HMMA proj
__device__ alignas(16) __nv_bfloat16 d_W_hi[384 * 256];
__device__ alignas(16) __nv_bfloat16 d_W_lo[384 * 256];
__device__ alignas(16) __nv_bfloat16 d_x_hi[B * C * N];   // [b][c][n]
__device__ alignas(16) __nv_bfloat16 d_x_lo[B * C * N];

// ============================================================================
// helpers
// ============================================================================
__device__ __forceinline__ uint32_t smem_u32(const void* p) {
    uint32_t a;
    asm("{ .reg .u64 t; cvta.to.shared.u64 t, %1; cvt.u32.u64 %0, t; }" : "=r"(a) : "l"(p));
    return a;
}
__device__ __forceinline__ uint16_t f2bf(float v) {
    return __bfloat16_as_ushort(__float2bfloat16(v));
}
__device__ __forceinline__ float bf2f(uint16_t u) {
    return __bfloat162float(__ushort_as_bfloat16(u));
}
__device__ __forceinline__ uint16_t f2h(float v) {
    return __half_as_ushort(__float2half_rn(v));
}
__device__ __forceinline__ float h2f(uint16_t u) {
    return __half2float(__ushort_as_half(u));
}
__device__ __forceinline__ uint32_t pack2(uint16_t lo, uint16_t hi) {
    return (uint32_t)lo | ((uint32_t)hi << 16);
}
__device__ __forceinline__ uint32_t f16x2(float lo, float hi) {
    __half2 h = __floats2half2_rn(lo, hi);
    return *reinterpret_cast<uint32_t*>(&h);
}
__device__ __forceinline__ void mma_bf16(float* c,
                                         uint32_t a0, uint32_t a1, uint32_t a2, uint32_t a3,
                                         uint32_t b0, uint32_t b1) {
    asm volatile(
        "mma.sync.aligned.m16n8k16.row.col.f32.bf16.bf16.f32 "
        "{%0,%1,%2,%3}, {%4,%5,%6,%7}, {%8,%9}, {%0,%1,%2,%3};"
        : "+f"(c[0]), "+f"(c[1]), "+f"(c[2]), "+f"(c[3])
        : "r"(a0), "r"(a1), "r"(a2), "r"(a3), "r"(b0), "r"(b1));
}
__device__ __forceinline__ void mma_f16(float* c,
                                        uint32_t a0, uint32_t a1, uint32_t a2, uint32_t a3,
                                        uint32_t b0, uint32_t b1) {
    asm volatile(
        "mma.sync.aligned.m16n8k16.row.col.f32.f16.f16.f32 "
        "{%0,%1,%2,%3}, {%4,%5,%6,%7}, {%8,%9}, {%0,%1,%2,%3};"
        : "+f"(c[0]), "+f"(c[1]), "+f"(c[2]), "+f"(c[3])
        : "r"(a0), "r"(a1), "r"(a2), "r"(a3), "r"(b0), "r"(b1));
}
__device__ __forceinline__ void ldsm_x4(uint32_t addr, uint32_t& r0, uint32_t& r1,
                                        uint32_t& r2, uint32_t& r3) {
    asm volatile("ldmatrix.sync.aligned.m8n8.x4.shared.b16 {%0,%1,%2,%3}, [%4];"
                 : "=r"(r0), "=r"(r1), "=r"(r2), "=r"(r3) : "r"(addr));
}
__device__ __forceinline__ void ldsm_x4_t(uint32_t addr, uint32_t& r0, uint32_t& r1,
                                          uint32_t& r2, uint32_t& r3) {
    asm volatile("ldmatrix.sync.aligned.m8n8.x4.trans.shared.b16 {%0,%1,%2,%3}, [%4];"
                 : "=r"(r0), "=r"(r1), "=r"(r2), "=r"(r3) : "r"(addr));
}
__device__ __forceinline__ void cp16(uint32_t saddr, const void* gaddr) {
    asm volatile("cp.async.cg.shared.global [%0], [%1], 16;" :: "r"(saddr), "l"(gaddr));
}
#define CP_COMMIT() asm volatile("cp.async.commit_group;" ::: "memory")
#define CP_WAIT(n)  asm volatile("cp.async.wait_group %0;" :: "n"(n) : "memory")

// ============================================================================
// K0a: split weights. grid 384 x 256.
// ============================================================================
__global__ void splitw_kernel(const float* __restrict__ w_g,
                              const float* __restrict__ w_t,
                              const float* __restrict__ w_p)
{
    int row = blockIdx.x, t = threadIdx.x;
    const float* src = (row < 128) ? w_g + (size_t)row * 256
                     : (row < 256) ? w_t + (size_t)(row - 128) * 256
                                   : w_p + (size_t)(row - 256) * 256;
    float v = src[t];
    uint16_t h = f2bf(v);
    d_W_hi[(size_t)row * 256 + t] = __ushort_as_bfloat16(h);
    d_W_lo[(size_t)row * 256 + t] = __ushort_as_bfloat16(f2bf(v - bf2f(h)));
}

// ============================================================================
// K0b: split x. grid 4096 x 256.
// ============================================================================
__global__ void splitx_kernel(const float* __restrict__ x)
{
    int idx4 = blockIdx.x * blockDim.x + threadIdx.x;
    float4 v = ((const float4*)x)[idx4];
    uint16_t h0 = f2bf(v.x), h1 = f2bf(v.y), h2 = f2bf(v.z), h3 = f2bf(v.w);
    *(uint2*)(d_x_hi + (size_t)idx4 * 4) = make_uint2(pack2(h0, h1), pack2(h2, h3));
    *(uint2*)(d_x_lo + (size_t)idx4 * 4) =
        make_uint2(pack2(f2bf(v.x - bf2f(h0)), f2bf(v.y - bf2f(h1))),
                   pack2(f2bf(v.z - bf2f(h2)), f2bf(v.w - bf2f(h3))));
}

// ============================================================================
// K1: HMMA projection GEMM (bf16 3-chain, fp16 outputs). grid (3,32,4), 256.
// mt: 0 -> g16 [b][c][m] hi+lo; 1 -> thT [b][n][ci] hi only; 2 -> phT hi+lo
// ============================================================================
#define PJ_WHI   0u
#define PJ_WLO   10240u
#define PJ_XHI   20480u
#define PJ_XLO   29184u
#define PJ_STAGE 37888u
#define PROJ_SMEM 75776

__global__ void __launch_bounds__(256, 2) proj_kernel(const float* __restrict__ b_g,
                                                      const float* __restrict__ b_t,
                                                      const float* __restrict__ b_p)
{
    extern __shared__ char smc[];
    const uint32_t sb = smem_u32(smc);
    const int mt = blockIdx.x;
    const int n0 = blockIdx.y * 128;
    const int b  = blockIdx.z;
    const int tid = threadIdx.x, wid = tid >> 5, lane = tid & 31;
    const int gid = lane >> 2, tig = lane & 3;
    const int obase = mt * 128;

    float acc[16][4];
#pragma unroll
    for (int nf = 0; nf < 16; nf++)
#pragma unroll
        for (int e = 0; e < 4; e++) acc[nf][e] = 0.f;

    auto load_chunk = [&](int st, int kc) {
        uint32_t base = sb + (uint32_t)st * PJ_STAGE;
        for (int idx = tid; idx < 512; idx += 256) {
            int r = idx >> 2, sg = idx & 3;
            cp16(base + PJ_WHI + (uint32_t)r * 80 + sg * 16,
                 d_W_hi + (size_t)(obase + r) * 256 + kc + sg * 8);
            cp16(base + PJ_WLO + (uint32_t)r * 80 + sg * 16,
                 d_W_lo + (size_t)(obase + r) * 256 + kc + sg * 8);
            int xr = idx >> 4, xs = idx & 15;
            cp16(base + PJ_XHI + (uint32_t)xr * 272 + xs * 16,
                 d_x_hi + (size_t)(b * C + kc + xr) * N + n0 + xs * 8);
            cp16(base + PJ_XLO + (uint32_t)xr * 272 + xs * 16,
                 d_x_lo + (size_t)(b * C + kc + xr) * N + n0 + xs * 8);
        }
    };

    load_chunk(0, 0);
    CP_COMMIT();
    for (int c = 0; c < 8; ++c) {
        if (c + 1 < 8) { load_chunk((c + 1) & 1, (c + 1) * 32); CP_COMMIT(); CP_WAIT(1); }
        else           { CP_WAIT(0); }
        __syncthreads();
        uint32_t base = sb + (uint32_t)(c & 1) * PJ_STAGE;
#pragma unroll
        for (int kk = 0; kk < 2; ++kk) {
            uint32_t aaddr = base + PJ_WHI + (uint32_t)(wid * 16 + (lane & 15)) * 80
                           + (uint32_t)(lane >> 4) * 16 + (uint32_t)kk * 32;
            uint32_t ah0, ah1, ah2, ah3, al0, al1, al2, al3;
            ldsm_x4(aaddr, ah0, ah1, ah2, ah3);
            ldsm_x4(aaddr + (PJ_WLO - PJ_WHI), al0, al1, al2, al3);
#pragma unroll
            for (int nf = 0; nf < 16; ++nf) {
                uint32_t baddr = base + PJ_XHI
                               + (uint32_t)(kk * 16 + ((lane >> 3) & 1) * 8 + (lane & 7)) * 272
                               + (uint32_t)(lane >> 4) * (PJ_XLO - PJ_XHI)
                               + (uint32_t)nf * 16;
                uint32_t bh0, bh1, bl0, bl1;
                ldsm_x4_t(baddr, bh0, bh1, bl0, bl1);
                mma_bf16(acc[nf], ah0, ah1, ah2, ah3, bh0, bh1);
                mma_bf16(acc[nf], ah0, ah1, ah2, ah3, bl0, bl1);
                mma_bf16(acc[nf], al0, al1, al2, al3, bh0, bh1);
            }
        }
        __syncthreads();
    }

    const float* bias = (mt == 0) ? b_g : (mt == 1) ? b_t : b_p;
    const int r0 = wid * 16 + gid, r1 = r0 + 8;
    const float br0 = bias[r0], br1 = bias[r1];
#pragma unroll
    for (int nf = 0; nf < 16; ++nf) {
        acc[nf][0] += br0; acc[nf][1] += br0;
        acc[nf][2] += br1; acc[nf][3] += br1;
    }

    if (mt == 0) {
        __half* dsts[2] = { d_g16_hi + (size_t)(b * CI) * N + n0,
                            d_g16_lo + (size_t)(b * CI) * N + n0 };
#pragma unroll
        for (int rnd = 0; rnd < 2; ++rnd) {
#pragma unroll
            for (int nf = 0; nf < 16; ++nf) {
                int ncol = 8 * nf + 2 * tig;
                uint16_t h0 = f2h(acc[nf][0]), h1 = f2h(acc[nf][1]);
                uint16_t h2 = f2h(acc[nf][2]), h3 = f2h(acc[nf][3]);
                uint32_t v0, v1;
                if (rnd == 0) { v0 = pack2(h0, h1); v1 = pack2(h2, h3); }
                else {
                    v0 = pack2(f2h(acc[nf][0] - h2f(h0)), f2h(acc[nf][1] - h2f(h1)));
                    v1 = pack2(f2h(acc[nf][2] - h2f(h2)), f2h(acc[nf][3] - h2f(h3)));
                }
                *(uint32_t*)(smc + (uint32_t)r0 * 272 + (uint32_t)ncol * 2) = v0;
                *(uint32_t*)(smc + (uint32_t)r1 * 272 + (uint32_t)ncol * 2) = v1;
            }
            __syncthreads();
            for (int idx = tid; idx < 2048; idx += 256) {
                int row = idx >> 4, c16 = idx & 15;
                *(uint4*)(dsts[rnd] + (size_t)row * N + c16 * 8) =
                    *(const uint4*)(smc + (uint32_t)row * 272 + (uint32_t)c16 * 16);
            }
            __syncthreads();
        }
    } else if (mt == 1) {
        __half* dst = d_thT;
#pragma unroll
        for (int nf = 0; nf < 16; ++nf) {
            int nc = 8 * nf + 2 * tig;
            *(uint16_t*)(smc + (uint32_t)(nc + 0) * 272 + (uint32_t)r0 * 2) = f2h(acc[nf][0]);
            *(uint16_t*)(smc + (uint32_t)(nc + 1) * 272 + (uint32_t)r0 * 2) = f2h(acc[nf][1]);
            *(uint16_t*)(smc + (uint32_t)(nc + 0) * 272 + (uint32_t)r1 * 2) = f2h(acc[nf][2]);
            *(uint16_t*)(smc + (uint32_t)(nc + 1) * 272 + (uint32_t)r1 * 2) = f2h(acc[nf][3]);
        }
        __syncthreads();
        for (int idx = tid; idx < 2048; idx += 256) {
            int row = idx >> 4, c16 = idx & 15;
            *(uint4*)(dst + (size_t)(b * N + n0 + row) * CI + c16 * 8) =
                *(const uint4*)(smc + (uint32_t)row * 272 + (uint32_t)c16 * 16);
        }
        __syncthreads();
    } else {
        __half* dsts[2] = { d_phT_hi, d_phT_lo };
#pragma unroll
        for (int rnd = 0; rnd < 2; ++rnd) {
#pragma unroll
            for (int nf = 0; nf < 16; ++nf) {
                int nc = 8 * nf + 2 * tig;
                uint16_t h0 = f2h(acc[nf][0]), h1 = f2h(acc[nf][1]);
                uint16_t h2 = f2h(acc[nf][2]), h3 = f2h(acc[nf][3]);
                uint16_t v0, v1, v2, v3;
                if (rnd == 0) { v0 = h0; v1 = h1; v2 = h2; v3 = h3; }
                else {
                    v0 = f2h(acc[nf][0] - h2f(h0)); v1 = f2h(acc[nf][1] - h2f(h1));
                    v2 = f2h(acc[nf][2] - h2f(h2)); v3 = f2h(acc[nf][3] - h2f(h3));
                }
                *(uint16_t*)(smc + (uint32_t)(nc + 0) * 272 + (uint32_t)r0 * 2) = v0;
                *(uint16_t*)(smc + (uint32_t)(nc + 1) * 272 + (uint32_t)r0 * 2) = v1;
                *(uint16_t*)(smc + (uint32_t)(nc + 0) * 272 + (uint32_t)r1 * 2) = v2;
                *(uint16_t*)(smc + (uint32_t)(nc + 1) * 272 + (uint32_t)r1 * 2) = v3;
            }
            __syncthreads();
            for (int idx = tid; idx < 2048; idx += 256) {
                int row = idx >> 4, c16 = idx & 15;
                *(uint4*)(dsts[rnd] + (size_t)(b * N + n0 + row) * CI + c16 * 8) =
                    *(const uint4*)(smc + (uint32_t)row * 272 + (uint32_t)c16 * 16);
            }
            __syncthreads();
        }
    }
}

// ============================================================================
// K2: HMMA fp16 flash attention — R11 structure, 2-chain arithmetic.
// 256 thr / 8 warps x 16 query rows. theta (hi fp16) in REGISTERS (32 regs).
// Per iter (m-tile 64): ONE __syncthreads.
//   QK: k-outer: for k(8) { for j(8) { ldsm B(phi hi+lo via sel); 2 mma } }
//   exp -> P fp16 packed in registers (accum layout == A-frag layout)
//   PV: kt-outer: for kt(4) { for ct(16) { ldsm G(hi+lo via sel); 2 mma } }
// grid (32, 4), dyn smem 143360 (2 stages x 71680), cp.async 2-stage.
// ============================================================================
#define ST_PHI_HI  0u
#define ST_PHI_LO  17408u
#define ST_G_HI    34816u
#define ST_G_LO    53248u
#define AT_STAGE   71680u
#define ATTN_SMEM  143360

__global__ void __launch_bounds__(256, 1) attn_kernel()
{
    extern __shared__ char smc[];
    const uint32_t sb = smem_u32(smc);
    const int b   = blockIdx.y;
    const int n0  = blockIdx.x * 128;
    const int tid = threadIdx.x;
    const int wid = tid >> 5, lane = tid & 31;
    const int gid = lane >> 2, tig = lane & 3;
    const int sel = lane >> 3, lr = lane & 7;

    auto stage_load = [&](int st, int it) {
        const int m0 = it * 64;
        uint32_t base = sb + (uint32_t)st * AT_STAGE;
        const __half* ph = d_phT_hi + (size_t)(b * N + m0) * CI;
        const __half* pl = d_phT_lo + (size_t)(b * N + m0) * CI;
        for (int idx = tid; idx < 64 * 16; idx += 256) {
            int r = idx >> 4, ch = idx & 15;
            uint32_t o = (uint32_t)r * 272 + (uint32_t)ch * 16;
            cp16(base + ST_PHI_HI + o, ph + (size_t)r * CI + ch * 8);
            cp16(base + ST_PHI_LO + o, pl + (size_t)r * CI + ch * 8);
        }
        const __half* gh = d_g16_hi + (size_t)b * CI * N + m0;
        const __half* gl = d_g16_lo + (size_t)b * CI * N + m0;
        for (int idx = tid; idx < 128 * 8; idx += 256) {
            int r = idx >> 3, ch = idx & 7;
            uint32_t o = (uint32_t)r * 144 + (uint32_t)ch * 16;
            cp16(base + ST_G_HI + o, gh + (size_t)r * N + ch * 8);
            cp16(base + ST_G_LO + o, gl + (size_t)r * N + ch * 8);
        }
    };

    stage_load(0, 0);
    CP_COMMIT();

    // ---- theta A-fragments (hi fp16) from gmem once: 32 regs ----
    uint32_t a[8][4];
    {
        const size_t rowbase = (size_t)(b * N + n0 + 16 * wid);
        const __half* th = d_thT + rowbase * CI;
        const int r0 = gid, r1 = gid + 8, c0 = 2 * tig;
#pragma unroll
        for (int k = 0; k < 8; k++) {
            a[k][0] = *(const uint32_t*)(th + (size_t)r0 * CI + 16 * k + c0);
            a[k][1] = *(const uint32_t*)(th + (size_t)r1 * CI + 16 * k + c0);
            a[k][2] = *(const uint32_t*)(th + (size_t)r0 * CI + 16 * k + c0 + 8);
            a[k][3] = *(const uint32_t*)(th + (size_t)r1 * CI + 16 * k + c0 + 8);
        }
    }

    float y[16][4];
#pragma unroll
    for (int t = 0; t < 16; t++)
#pragma unroll
        for (int e = 0; e < 4; e++) y[t][e] = 0.f;
    float l_lo = 0.f, l_hi = 0.f;

    for (int it = 0; it < 64; ++it) {
        if (it + 1 < 64) { stage_load((it + 1) & 1, it + 1); CP_COMMIT(); CP_WAIT(1); }
        else             { CP_WAIT(0); }
        __syncthreads();  // single barrier per iteration
        const uint32_t stb = sb + (uint32_t)(it & 1) * AT_STAGE;

        // ---- QK: S[16 x 64], 2 chains (A_hi x B_hi + A_hi x B_lo) ----
        float s[8][4];
#pragma unroll
        for (int j = 0; j < 8; j++)
#pragma unroll
            for (int e = 0; e < 4; e++) s[j][e] = 0.f;

#pragma unroll
        for (int k = 0; k < 8; k++) {
#pragma unroll
            for (int j = 0; j < 8; j++) {
                uint32_t addr = stb + ((sel >= 2) ? ST_PHI_LO : ST_PHI_HI)
                              + (uint32_t)(8 * j + lr) * 272
                              + (uint32_t)k * 32 + (uint32_t)(sel & 1) * 16;
                uint32_t bh0, bh1, bl0, bl1;
                ldsm_x4(addr, bh0, bh1, bl0, bl1);
                mma_f16(s[j], a[k][0], a[k][1], a[k][2], a[k][3], bh0, bh1);
                mma_f16(s[j], a[k][0], a[k][1], a[k][2], a[k][3], bl0, bl1);
            }
        }

        // ---- exp + rowsum + pack P fragments (registers only) ----
        float rs0 = 0.f, rs1 = 0.f;
        uint32_t pa[4][4];
#pragma unroll
        for (int j = 0; j < 8; j++) {
#pragma unroll
            for (int e = 0; e < 4; e++) s[j][e] = __expf(s[j][e]);
            rs0 += s[j][0] + s[j][1];
            rs1 += s[j][2] + s[j][3];
        }
#pragma unroll
        for (int kt = 0; kt < 4; kt++) {
            const int j0 = 2 * kt, j1 = 2 * kt + 1;
            pa[kt][0] = f16x2(s[j0][0], s[j0][1]);
            pa[kt][1] = f16x2(s[j0][2], s[j0][3]);
            pa[kt][2] = f16x2(s[j1][0], s[j1][1]);
            pa[kt][3] = f16x2(s[j1][2], s[j1][3]);
        }
        rs0 += __shfl_xor_sync(0xffffffffu, rs0, 1);
        rs0 += __shfl_xor_sync(0xffffffffu, rs0, 2);
        rs1 += __shfl_xor_sync(0xffffffffu, rs1, 1);
        rs1 += __shfl_xor_sync(0xffffffffu, rs1, 2);
        l_lo += rs0;
        l_hi += rs1;

        // ---- PV: Y[16 x 128], 2 chains (P x G_hi + P x G_lo) ----
#pragma unroll
        for (int kt = 0; kt < 4; kt++) {
#pragma unroll
            for (int ct = 0; ct < 16; ct++) {
                uint32_t addr = stb + ((sel >= 2) ? ST_G_LO : ST_G_HI)
                              + (uint32_t)(8 * ct + lr) * 144
                              + (uint32_t)kt * 32 + (uint32_t)(sel & 1) * 16;
                uint32_t gh0, gh1, gl0, gl1;
                ldsm_x4(addr, gh0, gh1, gl0, gl1);
                mma_f16(y[ct], pa[kt][0], pa[kt][1], pa[kt][2], pa[kt][3], gh0, gh1);
                mma_f16(y[ct], pa[kt][0], pa[kt][1], pa[kt][2], pa[kt][3], gl0, gl1);
            }
        }
        __syncthreads();  // protect stage for next iter's cp.async
    }

    // ---- normalize + transpose via smem -> coalesced d_y [b][c][n] ----
    float* ysm = (float*)smc;  // [128 c][pitch 132] floats (overlays stages)
    const float inv0 = 1.f / l_lo, inv1 = 1.f / l_hi;
    const int nl0 = 16 * wid + gid, nl1 = nl0 + 8;
#pragma unroll
    for (int ct = 0; ct < 16; ct++) {
        int c = 8 * ct + 2 * tig;
        ysm[(c + 0) * 132 + nl0] = y[ct][0] * inv0;
        ysm[(c + 1) * 132 + nl0] = y[ct][1] * inv0;
        ysm[(c + 0) * 132 + nl1] = y[ct][2] * inv1;
        ysm[(c + 1) * 132 + nl1] = y[ct][3] * inv1;
    }
    __syncthreads();
    for (int idx = tid; idx < 128 * 128; idx += 256) {
        int c = idx >> 7, n = idx & 127;
        d_y[(size_t)(b * CI + c) * N + n0 + n] = ysm[c * 132 + n];
    }
}

// ============================================================================
// K3: W_y = w_out @ y + b_out + deterministic BN partials. grid (4,32,4), 256.
// ============================================================================
__global__ void wy_kernel(const float* __restrict__ w_out, const float* __restrict__ b_out)
{
    __shared__ float Ws[32][65];
    __shared__ float Ys[32][128];
    const int b  = blockIdx.z;
    const int n0 = blockIdx.y * 128;
    const int o0 = blockIdx.x * 64;
    const int tid = threadIdx.x;
    const int tx = tid & 15, ty = tid >> 4;

    float acc[4][8];
#pragma unroll
    for (int i = 0; i < 4; i++)
#pragma unroll
        for (int j = 0; j < 8; j++) acc[i][j] = 0.f;

    for (int kc = 0; kc < CI; kc += 32) {
        for (int idx = tid; idx < 64 * 32; idx += 256) {
            int o = idx >> 5, k = idx & 31;
            Ws[k][o] = w_out[(o0 + o) * CI + kc + k];
        }
        for (int idx = tid; idx < 32 * 128; idx += 256) {
            int k = idx >> 7, n = idx & 127;
            Ys[k][n] = d_y[(size_t)(b * CI + kc + k) * N + n0 + n];
        }
        __syncthreads();
#pragma unroll 4
        for (int k = 0; k < 32; k++) {
            float a0 = Ws[k][ty * 4 + 0], a1 = Ws[k][ty * 4 + 1];
            float a2 = Ws[k][ty * 4 + 2], a3 = Ws[k][ty * 4 + 3];
            const float4 v0 = *(const float4*)&Ys[k][tx * 8];
            const float4 v1 = *(const float4*)&Ys[k][tx * 8 + 4];
            float bv[8] = {v0.x, v0.y, v0.z, v0.w, v1.x, v1.y, v1.z, v1.w};
#pragma unroll
            for (int j = 0; j < 8; j++) {
                acc[0][j] += a0 * bv[j];
                acc[1][j] += a1 * bv[j];
                acc[2][j] += a2 * bv[j];
                acc[3][j] += a3 * bv[j];
            }
        }
        __syncthreads();
    }

#pragma unroll
    for (int i = 0; i < 4; i++) {
        int oc = o0 + ty * 4 + i;
        float bb = b_out[oc];
        float s = 0.f, q = 0.f;
        float* p = d_wy + (size_t)(b * C + oc) * N + n0 + tx * 8;
#pragma unroll
        for (int j = 0; j < 8; j++) {
            float vv = acc[i][j] + bb;
            p[j] = vv;
            s += vv;
            q += vv * vv;
        }
#pragma unroll
        for (int off = 1; off < 16; off <<= 1) {
            s += __shfl_xor_sync(0xffffffffu, s, off);
            q += __shfl_xor_sync(0xffffffffu, q, off);
        }
        if (tx == 0) {
            int part = b * 32 + blockIdx.y;
            d_psum[oc * 128 + part] = s;
            d_psq[oc * 128 + part]  = q;
        }
    }
}

// ============================================================================
// K4: reduce BN partials. grid 256, 32 threads.
// ============================================================================
__global__ void bnstat_kernel(const float* __restrict__ gamma, const float* __restrict__ beta)
{
    int c = blockIdx.x, t = threadIdx.x;
    float s = 0.f, q = 0.f;
#pragma unroll
    for (int p = t; p < 128; p += 32) {
        s += d_psum[c * 128 + p];
        q += d_psq[c * 128 + p];
    }
#pragma unroll
    for (int off = 1; off < 32; off <<= 1) {
        s += __shfl_xor_sync(0xffffffffu, s, off);
        q += __shfl_xor_sync(0xffffffffu, q, off);
    }
    if (t == 0) {
        const float invn = 1.f / 16384.f;
        float mean = s * invn;
        float var  = q * invn - mean * mean;
        float sc   = gamma[c] * rsqrtf(var + 1e-5f);
        d_bnA[c] = sc;
        d_bnB[c] = beta[c] - mean * sc;
    }
}

// ============================================================================
// K5: out = W_y * scale[c] + shift[c] + x
// ============================================================================
__global__ void bnadd_kernel(const float* __restrict__ x, float* __restrict__ out)
{
    int idx4 = blockIdx.x * blockDim.x + threadIdx.x;
    if (idx4 >= B * C * N / 4) return;
    int c = (idx4 >> 10) & (C - 1);
    float sc = d_bnA[c], bb = d_bnB[c];
    float4 w  = ((const float4*)d_wy)[idx4];
    float4 xv = ((const float4*)x)[idx4];
    float4 r;
    r.x = w.x * sc + bb + xv.x;
    r.y = w.y * sc + bb + xv.y;
    r.z = w.z * sc + bb + xv.z;
    r.w = w.w * sc + bb + xv.w;
    ((float4*)out)[idx4] = r;
}

// ============================================================================
extern "C" void kernel_launch(void* const* d_in, const int* in_sizes, int n_in,
                              void* d_out, int out_size)
{
    const float* x     = (const float*)d_in[0];
    const float* w_g   = (const float*)d_in[1];
    const float* b_g   = (const float*)d_in[2];
    const float* w_t   = (const float*)d_in[3];
    const float* b_t   = (const float*)d_in[4];
    const float* w_p   = (const float*)d_in[5];
    const float* b_p   = (const float*)d_in[6];
    const float* w_o   = (const float*)d_in[7];
    const float* b_o   = (const float*)d_in[8];
    const float* gamma = (const float*)d_in[9];
    const float* beta  = (const float*)d_in[10];
    float* out = (float*)d_out;

    cudaFuncSetAttribute(proj_kernel, cudaFuncAttributeMaxDynamicSharedMemorySize, PROJ_SMEM);
    cudaFuncSetAttribute(attn_kernel, cudaFuncAttributeMaxDynamicSharedMemorySize, ATTN_SMEM);

    splitw_kernel<<<384, 256>>>(w_g, w_t, w_p);
    splitx_kernel<<<4096, 256>>>(x);
    proj_kernel<<<dim3(3, 32, 4), 256, PROJ_SMEM>>>(b_g, b_t, b_p);
    attn_kernel<<<dim3(32, 4), 256, ATTN_SMEM>>>();
    wy_kernel<<<dim3(4, 32, 4), 256>>>(w_o, b_o);
    bnstat_kernel<<<256, 32>>>(gamma, beta);
    bnadd_kernel<<<4096, 256>>>(x, out);
}